// round 15
// baseline (speedup 1.0000x reference)
#include <cuda_runtime.h>
#include <cuda_fp16.h>

// HausdorffDTLoss, [4,1,256,256] fp32. Two kernels, one stream, all-fp32.
// loss = mean( (pred-target)^2 * (pred_dt^2 + target_dt^2) ),
// dt^2(pixel) = squared distance to nearest opposite-class pixel
//   (= edt(fg)^2 + edt(~fg)^2 with exactly one term nonzero; BIG-clamped).
// Stage 1 (vertical): nearest-opposite-bit search on ballot-packed column
//   masks (ffs/clz). Signed fp16 distance (+fg/-bg), +/-inf if none.
//   R10 config verbatim: 1024 blocks x 512 threads, 1 search/thread.
// Stage 2 (horizontal): windowed min-plus over the OWN field only (the
//   other field is identically 0 at every site). R12 config verbatim:
//   512 blocks x 512 threads, scalar tile load, 2 scans/thread (ILP-2),
//   d=1,2 straight-line (extras dominated), pipelined tail, per-lane exit.
// Exactness: every candidate is g_j^2 + d^2 in fp32 on exact integers;
// d^2 >= m can't win; clamped-index re-evaluations are dominated.

#define BIGF 1e10f
#define HW 256
#define IMG 65536
#define TOTAL 262144
#define RS 584      // smem row stride, floats (RS%32==8 -> store banks ok)
#define AO 288      // Ubg offset within row (AO%32==0 -> same banks as Ufg)
#define NBLK2 512

// [img(2)][b(4)][x][y] signed vertical distance (fp16, y fast; transposed)
__device__ __align__(16) __half g_V[2 * 4 * IMG];
__device__ int g_fgany[8];          // [img*4 + b]; zero-init, self-reset
__device__ float g_accum;           // zero-init, self-reset
__device__ unsigned int g_counter;  // zero-init, self-reset

// ---------------------------------------------------------------------------
// Stage 1 (R10 verbatim): 1024 blocks x 512 threads.
// Block = (img, b, 2-column tile). Threads 0..255 load float2 + ballot the
// two column masks; then all 512 threads each run ONE nearest-opposite-bit
// search (k = tid>>8, y = tid&255).
// ---------------------------------------------------------------------------
__global__ __launch_bounds__(512) void stage1_kernel(
    const float* __restrict__ pred, const float* __restrict__ target)
{
    __shared__ unsigned msk[2][8];
    __shared__ unsigned sany[8];

    int bid = blockIdx.x;            // 0..1023
    int xt  = bid & 127;
    int b   = (bid >> 7) & 3;
    int img = bid >> 9;
    int x0  = xt * 2;
    int tid = threadIdx.x;

    if (tid < 256) {
        int y  = tid;
        int w0 = y >> 5, lb = y & 31;
        const float* im = (img ? target : pred) + b * IMG + y * HW + x0;
        float2 v = *reinterpret_cast<const float2*>(im);   // coalesced 8B
        unsigned b0 = __ballot_sync(~0u, v.x > 0.5f);
        unsigned b1 = __ballot_sync(~0u, v.y > 0.5f);
        if (lb == 0) { msk[0][w0] = b0; msk[1][w0] = b1; sany[w0] = b0 | b1; }
    }
    __syncthreads();

    if (tid == 0) {                  // one fire-and-forget RED per block
        unsigned o = 0;
        #pragma unroll
        for (int k = 0; k < 8; ++k) o |= sany[k];
        if (o) atomicOr(&g_fgany[img * 4 + b], 1);
    }

    int k  = tid >> 8;               // column within tile (0/1)
    int y  = tid & 255;
    int w0 = y >> 5, lb = y & 31;
    const unsigned* M = msk[k];
    unsigned W0 = M[w0];
    bool cls = (W0 >> lb) & 1u;      // own class of this site
    unsigned inv = cls ? 0xFFFFFFFFu : 0u;
    unsigned T0 = W0 ^ inv;          // 1-bits = opposite class

    int dup = 1 << 20;               // search up (y+1..255)
    unsigned rem = T0 & (0xFFFFFFFEu << lb);
    if (rem) dup = __ffs(rem) - 1 - lb;
    else {
        #pragma unroll 1
        for (int w = w0 + 1; w < 8; ++w) {
            unsigned tw = M[w] ^ inv;
            if (tw) { dup = ((w - w0) << 5) + __ffs(tw) - 1 - lb; break; }
        }
    }
    int ddn = 1 << 20;               // search down (y-1..0)
    rem = T0 & ((1u << lb) - 1u);
    if (rem) ddn = lb + __clz(rem) - 31;
    else {
        #pragma unroll 1
        for (int w = w0 - 1; w >= 0; --w) {
            unsigned tw = M[w] ^ inv;
            if (tw) { ddn = ((w0 - w) << 5) + lb + __clz(tw) - 31; break; }
        }
    }
    int g = min(dup, ddn);           // >= 1
    float gf = (g > 256) ? BIGF : (float)g;       // BIGF -> fp16 inf
    g_V[(img * 4 + b) * IMG + (x0 + k) * HW + y] =
        __float2half(cls ? gf : -gf);             // 64B per warp
}

// ---------------------------------------------------------------------------
// Stage 2 (R12 verbatim): 512 blocks x 512 threads. Block = (img, b,
// 4-row tile). Tile load decodes signed field into Ufg/Ubg rows. Thread
// (q = tid>>8, x = tid&255) scans rows 2q, 2q+1 jointly (ILP-2):
// d=1,2 straight-line, pipelined tail with per-lane exit. Then loss,
// block reduce, last block finalizes + resets.
// ---------------------------------------------------------------------------
__global__ __launch_bounds__(512, 3) void stage2_kernel(
    const float* __restrict__ pred, const float* __restrict__ target,
    float* __restrict__ out)
{
    __shared__ __align__(16) float s[4 * RS];    // 4 rows x (Ufg | Ubg)

    int bid = blockIdx.x;            // 0..511
    int yt  = bid & 63;
    int b   = (bid >> 6) & 3;
    int img = bid >> 8;
    int y0  = yt * 4;
    int tid = threadIdx.x;

    const __half* V = g_V + (img * 4 + b) * IMG;   // [x][y] layout
    #pragma unroll
    for (int it = 0; it < 2; ++it) {
        int idx = it * 512 + tid;
        int x = idx >> 2, r = idx & 3;             // 4 consecutive halfs per x
        float v = __half2float(V[x * HW + y0 + r]);
        s[r * RS + x]      = fmaxf(v, 0.0f);       // Ufg
        s[r * RS + AO + x] = fmaxf(-v, 0.0f);      // Ubg
    }
    __syncthreads();

    int q = tid >> 8;                // rows 2q, 2q+1
    int x = tid & 255;

    const float* R0 = s + (2 * q) * RS;
    const float* R1 = R0 + RS;
    float vf0 = R0[x], vb0 = R0[AO + x];
    float vf1 = R1[x], vb1 = R1[AO + x];
    bool  cA = vf0 > 0.0f;           // own class (|v| >= 1, never 0)
    bool  cB = vf1 > 0.0f;
    const float* PA = cA ? R0 : (R0 + AO);
    const float* PB = cB ? R1 : (R1 + AO);
    float uA = cA ? vf0 : vb0;  float mA = uA * uA;   // own candidate g^2
    float uB = cB ? vf1 : vb1;  float mB = uB * uB;

    // d = 1, 2 straight-line (no exit checks; extras are dominated)
    {
        int l1 = x >= 1 ? x - 1 : 0, r1 = x <= 254 ? x + 1 : 255;
        int l2 = x >= 2 ? x - 2 : 0, r2 = x <= 253 ? x + 2 : 255;
        float a1 = fminf(PA[l1], PA[r1]);
        float b1 = fminf(PB[l1], PB[r1]);
        mA = fminf(mA, __fmaf_rn(a1, a1, 1.0f));
        mB = fminf(mB, __fmaf_rn(b1, b1, 1.0f));
        float a2 = fminf(PA[l2], PA[r2]);
        float b2 = fminf(PB[l2], PB[r2]);
        mA = fminf(mA, __fmaf_rn(a2, a2, 4.0f));
        mB = fminf(mB, __fmaf_rn(b2, b2, 4.0f));
    }
    // pipelined tail: candidates for iteration d prefetched at d-1
    float d2 = 9.0f, st = 7.0f;      // d2 = d*d, st = 2d+1 (exact fp32)
    int il = x >= 3 ? x - 3 : 0;
    int ir = x <= 252 ? x + 3 : 255;
    float al = PA[il], ar = PA[ir];
    float bl = PB[il], br = PB[ir];
    #pragma unroll 1
    for (int d = 3; d < 256; ++d) {
        if (d2 >= fmaxf(mA, mB)) break;   // no farther candidate can win
        float ua = fminf(al, ar);
        float ub = fminf(bl, br);
        il = (x - d - 1) > 0 ? (x - d - 1) : 0;      // prefetch d+1
        ir = (x + d + 1) < 255 ? (x + d + 1) : 255;
        al = PA[il]; ar = PA[ir];
        bl = PB[il]; br = PB[ir];
        mA = fminf(mA, __fmaf_rn(ua, ua, d2));
        mB = fminf(mB, __fmaf_rn(ub, ub, d2));
        d2 += st; st += 2.0f;
    }

    int fg = g_fgany[img * 4 + b];
    const float* pr = pred + b * IMG;
    const float* tg = target + b * IMG;
    int i0 = (y0 + 2 * q) * HW + x;
    float e0 = pr[i0] - tg[i0];
    float e1 = pr[i0 + HW] - tg[i0 + HW];
    float acc = e0 * e0 * fminf(mA, BIGF) + e1 * e1 * fminf(mB, BIGF);
    if (!fg) acc = 0.0f;             // empty-foreground image contributes 0

    // Warp tree reduce, then 16 warp sums via reused smem.
    #pragma unroll
    for (int o = 16; o > 0; o >>= 1)
        acc += __shfl_down_sync(0xFFFFFFFFu, acc, o);

    __syncthreads();                 // done reading s
    float* ws = s;
    int wid = tid >> 5, lane = tid & 31;
    if (lane == 0) ws[wid] = acc;
    __syncthreads();

    if (tid == 0) {
        float s0 = 0.f, s1 = 0.f, s2 = 0.f, s3 = 0.f;   // 4-way tree
        #pragma unroll
        for (int w = 0; w < 16; w += 4) {
            s0 += ws[w]; s1 += ws[w + 1]; s2 += ws[w + 2]; s3 += ws[w + 3];
        }
        atomicAdd(&g_accum, (s0 + s1) + (s2 + s3));
        __threadfence();
        unsigned done = atomicAdd(&g_counter, 1u);
        if (done == NBLK2 - 1) {
            float tot = atomicAdd(&g_accum, 0.0f);      // coherent read
            out[0] = tot * (1.0f / (float)TOTAL);
            // Self-reset device state for the next graph replay.
            g_accum = 0.0f;
            g_counter = 0u;
            #pragma unroll
            for (int i2 = 0; i2 < 8; ++i2) g_fgany[i2] = 0;
        }
    }
}

extern "C" void kernel_launch(void* const* d_in, const int* in_sizes, int n_in,
                              void* d_out, int out_size) {
    const float* pred   = (const float*)d_in[0];
    const float* target = (const float*)d_in[1];
    float* out = (float*)d_out;

    stage1_kernel<<<1024, 512>>>(pred, target);
    stage2_kernel<<<NBLK2, 512>>>(pred, target, out);
}

// round 16
// speedup vs baseline: 1.2113x; 1.2113x over previous
#include <cuda_runtime.h>

// HausdorffDTLoss, [4,1,256,256] fp32. Two kernels, one stream, all-fp32.
// loss = mean( (pred-target)^2 * (pred_dt^2 + target_dt^2) ),
// dt^2(pixel) = squared distance to nearest opposite-class pixel
//   (= edt(fg)^2 + edt(~fg)^2 with exactly one term nonzero; BIG-clamped).
// Kernel A (maskgen): coalesced 128B row loads + ballot -> row masks; warp
//   32x32 bit transpose (shfl_xor, 5 steps) -> column-mask words. 64KB out.
// Kernel B: per (img, b, 4-row tile) block: load the image's 8KB column
//   mask (L2-hot), per-site nearest-opposite-bit vertical search (ffs/clz)
//   writing fp32 Ufg/Ubg smem rows directly (no g_V intermediate), then
//   the R12 horizontal windowed min-plus scan (d=1,2 straight-line,
//   pipelined tail, per-lane early exit), loss, block reduce, finalize.
// Exactness: every candidate is g_j^2 + d^2 in fp32 on exact integers;
// d^2 >= m can't win; clamped-index re-evaluations are dominated.

#define BIGF 1e10f
#define HW 256
#define IMG 65536
#define TOTAL 262144
#define RS 584      // smem row stride, floats (RS%32==8 -> store banks ok)
#define AO 288      // Ubg offset within row (AO%32==0 -> same banks as Ufg)
#define NBLKB 512

// Column masks: [img(2)][b(4)][w(8)][x(256)] uint32; bit r of word (w,x) =
// (pixel(y=32w+r, x) > 0.5). 64KB total.
__device__ __align__(16) unsigned g_M[2 * 4 * 8 * 256];
__device__ int g_fgany[8];          // [img*4 + b]; zero-init, self-reset
__device__ float g_accum;           // zero-init, self-reset
__device__ unsigned int g_counter;  // zero-init, self-reset

// ---------------------------------------------------------------------------
// Kernel A: 64 blocks x 256 threads. Block = (img, b, 32-row stripe).
// Warp w = 32x32 tile (cols 32w..32w+31). Coalesced loads, ballot row
// masks, warp bit-transpose, one coalesced word store per lane.
// ---------------------------------------------------------------------------
__global__ __launch_bounds__(256) void maskgen_kernel(
    const float* __restrict__ pred, const float* __restrict__ target)
{
    __shared__ unsigned wany[8];

    int bid   = blockIdx.x;          // 0..63
    int ytile = bid & 7;
    int b     = (bid >> 3) & 3;
    int img   = bid >> 5;
    int tid   = threadIdx.x;
    int wp    = tid >> 5;            // warp = xtile 0..7
    int lane  = tid & 31;
    int y0    = ytile * 32;
    int x0    = wp * 32;

    const float* im = (img ? target : pred) + b * IMG + y0 * HW + x0 + lane;

    unsigned x = 0, any = 0;
    #pragma unroll
    for (int rr = 0; rr < 32; ++rr) {
        float p = im[rr * HW];                       // 128B coalesced
        unsigned bal = __ballot_sync(~0u, p > 0.5f); // row y0+rr bits (bit=col)
        any |= bal;
        if (lane == rr) x = bal;                     // lane rr keeps row rr
    }

    // 32x32 bit transpose: after this, lane c bit r = pixel(y0+r, x0+c).
    #pragma unroll
    for (int j = 16; j > 0; j >>= 1) {
        unsigned m = 0xFFFFFFFFu / ((1u << j) + 1u); // compile-time constant
        unsigned y = __shfl_xor_sync(~0u, x, j);
        x = (lane & j) ? ((x & ~m) | ((y & ~m) >> j))
                       : ((x &  m) | ((y &  m) << j));
    }

    g_M[((img * 4 + b) * 8 + ytile) * 256 + x0 + lane] = x;  // coalesced

    if (lane == 0) wany[wp] = any;   // ballot results are warp-uniform
    __syncthreads();
    if (tid == 0) {
        unsigned o = 0;
        #pragma unroll
        for (int k = 0; k < 8; ++k) o |= wany[k];
        if (o) atomicOr(&g_fgany[img * 4 + b], 1);
    }
}

// ---------------------------------------------------------------------------
// Kernel B: 512 blocks x 512 threads. Block = (img, b, 4-row tile).
// Phase 1: load 8KB column mask into smem (uint4 per thread, L2-hot).
// Phase 2: thread (q = tid>>8, x = tid&255) does nearest-opposite-bit
//   vertical searches for rows 2q, 2q+1 at column x -> Ufg/Ubg smem rows.
// Phase 3: R12 horizontal scan of rows 2q,2q+1 (ILP-2), loss, reduce.
// ---------------------------------------------------------------------------
__global__ __launch_bounds__(512, 3) void fusedB_kernel(
    const float* __restrict__ pred, const float* __restrict__ target,
    float* __restrict__ out)
{
    __shared__ __align__(16) unsigned M[2048];   // [w(8)][x(256)]
    __shared__ __align__(16) float s[4 * RS];    // 4 rows x (Ufg | Ubg)

    int bid = blockIdx.x;            // 0..511
    int yt  = bid & 63;
    int b   = (bid >> 6) & 3;
    int img = bid >> 8;
    int y0  = yt * 4;
    int tid = threadIdx.x;
    int q   = tid >> 8;              // rows 2q, 2q+1
    int x   = tid & 255;

    // Phase 1: mask load (8KB, coalesced uint4; L2-hot after first block)
    {
        const uint4* gm = reinterpret_cast<const uint4*>(
            g_M + (img * 4 + b) * 2048);
        reinterpret_cast<uint4*>(M)[tid] = gm[tid];
    }
    __syncthreads();

    // Phase 2: vertical searches for this thread's two sites.
    #pragma unroll
    for (int j = 0; j < 2; ++j) {
        int y  = y0 + 2 * q + j;
        int w0 = y >> 5, lb = y & 31;
        unsigned W0 = M[w0 * 256 + x];
        bool cls = (W0 >> lb) & 1u;          // own class of this site
        unsigned inv = cls ? 0xFFFFFFFFu : 0u;
        unsigned T0 = W0 ^ inv;              // 1-bits = opposite class

        int dup = 1 << 20;                   // search up (y+1..255)
        unsigned rem = T0 & (0xFFFFFFFEu << lb);
        if (rem) dup = __ffs(rem) - 1 - lb;
        else {
            #pragma unroll 1
            for (int w = w0 + 1; w < 8; ++w) {
                unsigned tw = M[w * 256 + x] ^ inv;
                if (tw) { dup = ((w - w0) << 5) + __ffs(tw) - 1 - lb; break; }
            }
        }
        int ddn = 1 << 20;                   // search down (y-1..0)
        rem = T0 & ((1u << lb) - 1u);
        if (rem) ddn = lb + __clz(rem) - 31;
        else {
            #pragma unroll 1
            for (int w = w0 - 1; w >= 0; --w) {
                unsigned tw = M[w * 256 + x] ^ inv;
                if (tw) { ddn = ((w0 - w) << 5) + lb + __clz(tw) - 31; break; }
            }
        }
        int g = min(dup, ddn);               // >= 1
        float gf = (g > 256) ? BIGF : (float)g;
        int r = 2 * q + j;
        s[r * RS + x]      = cls ? gf : 0.0f;    // Ufg
        s[r * RS + AO + x] = cls ? 0.0f : gf;    // Ubg
    }
    __syncthreads();

    // Phase 3: horizontal scan (R12 verbatim).
    const float* R0 = s + (2 * q) * RS;
    const float* R1 = R0 + RS;
    float vf0 = R0[x], vb0 = R0[AO + x];
    float vf1 = R1[x], vb1 = R1[AO + x];
    bool  cA = vf0 > 0.0f;           // own class (gf >= 1, never 0)
    bool  cB = vf1 > 0.0f;
    const float* PA = cA ? R0 : (R0 + AO);
    const float* PB = cB ? R1 : (R1 + AO);
    float uA = cA ? vf0 : vb0;  float mA = uA * uA;   // own candidate g^2
    float uB = cB ? vf1 : vb1;  float mB = uB * uB;

    // d = 1, 2 straight-line (no exit checks; extras are dominated)
    {
        int l1 = x >= 1 ? x - 1 : 0, r1 = x <= 254 ? x + 1 : 255;
        int l2 = x >= 2 ? x - 2 : 0, r2 = x <= 253 ? x + 2 : 255;
        float a1 = fminf(PA[l1], PA[r1]);
        float b1 = fminf(PB[l1], PB[r1]);
        mA = fminf(mA, __fmaf_rn(a1, a1, 1.0f));
        mB = fminf(mB, __fmaf_rn(b1, b1, 1.0f));
        float a2 = fminf(PA[l2], PA[r2]);
        float b2 = fminf(PB[l2], PB[r2]);
        mA = fminf(mA, __fmaf_rn(a2, a2, 4.0f));
        mB = fminf(mB, __fmaf_rn(b2, b2, 4.0f));
    }
    // pipelined tail: candidates for iteration d prefetched at d-1
    float d2 = 9.0f, st = 7.0f;      // d2 = d*d, st = 2d+1 (exact fp32)
    int il = x >= 3 ? x - 3 : 0;
    int ir = x <= 252 ? x + 3 : 255;
    float al = PA[il], ar = PA[ir];
    float bl = PB[il], br = PB[ir];
    #pragma unroll 1
    for (int d = 3; d < 256; ++d) {
        if (d2 >= fmaxf(mA, mB)) break;   // no farther candidate can win
        float ua = fminf(al, ar);
        float ub = fminf(bl, br);
        il = (x - d - 1) > 0 ? (x - d - 1) : 0;      // prefetch d+1
        ir = (x + d + 1) < 255 ? (x + d + 1) : 255;
        al = PA[il]; ar = PA[ir];
        bl = PB[il]; br = PB[ir];
        mA = fminf(mA, __fmaf_rn(ua, ua, d2));
        mB = fminf(mB, __fmaf_rn(ub, ub, d2));
        d2 += st; st += 2.0f;
    }

    int fg = g_fgany[img * 4 + b];
    const float* pr = pred + b * IMG;
    const float* tg = target + b * IMG;
    int i0 = (y0 + 2 * q) * HW + x;
    float e0 = pr[i0] - tg[i0];
    float e1 = pr[i0 + HW] - tg[i0 + HW];
    float acc = e0 * e0 * fminf(mA, BIGF) + e1 * e1 * fminf(mB, BIGF);
    if (!fg) acc = 0.0f;             // empty-foreground image contributes 0

    // Warp tree reduce, then 16 warp sums via reused smem.
    #pragma unroll
    for (int o = 16; o > 0; o >>= 1)
        acc += __shfl_down_sync(0xFFFFFFFFu, acc, o);

    __syncthreads();                 // done reading s
    float* ws = s;
    int wid = tid >> 5, lane = tid & 31;
    if (lane == 0) ws[wid] = acc;
    __syncthreads();

    if (tid == 0) {
        float s0 = 0.f, s1 = 0.f, s2 = 0.f, s3 = 0.f;   // 4-way tree
        #pragma unroll
        for (int w = 0; w < 16; w += 4) {
            s0 += ws[w]; s1 += ws[w + 1]; s2 += ws[w + 2]; s3 += ws[w + 3];
        }
        atomicAdd(&g_accum, (s0 + s1) + (s2 + s3));
        __threadfence();
        unsigned done = atomicAdd(&g_counter, 1u);
        if (done == NBLKB - 1) {
            float tot = atomicAdd(&g_accum, 0.0f);      // coherent read
            out[0] = tot * (1.0f / (float)TOTAL);
            // Self-reset device state for the next graph replay.
            g_accum = 0.0f;
            g_counter = 0u;
            #pragma unroll
            for (int i2 = 0; i2 < 8; ++i2) g_fgany[i2] = 0;
        }
    }
}

extern "C" void kernel_launch(void* const* d_in, const int* in_sizes, int n_in,
                              void* d_out, int out_size) {
    const float* pred   = (const float*)d_in[0];
    const float* target = (const float*)d_in[1];
    float* out = (float*)d_out;

    maskgen_kernel<<<64, 256>>>(pred, target);
    fusedB_kernel<<<NBLKB, 512>>>(pred, target, out);
}